// round 2
// baseline (speedup 1.0000x reference)
#include <cuda_runtime.h>
#include <cstdint>

// Problem dims
#define M_DIM 4096   // 2*2048 rows of x
#define N_DIM 4096   // output features (rows of W)
#define K_DIM 4096   // reduction

// Scratch (allocation-free rule: __device__ globals)
__device__ float g_fqw[(size_t)N_DIM * (size_t)K_DIM];   // fake-quantized, tf32-rounded W
__device__ float g_xr [(size_t)M_DIM * (size_t)K_DIM];   // tf32-rounded x

// ---------------------------------------------------------------------------
// Kernel 1: Q4_K_M fake-quant of W, one CTA (256 thr) per 256-elem block.
// sub = warp (8 sub-blocks of 32), lane = element within sub-block.
// ---------------------------------------------------------------------------
__global__ void dequant_kernel(const float* __restrict__ W)
{
    __shared__ float s_scale_raw[8];
    __shared__ float s_mn[8];

    const int tid  = threadIdx.x;
    const int sub  = tid >> 5;
    const int lane = tid & 31;
    const size_t base = (size_t)blockIdx.x * 256u;

    float w = W[base + tid];

    // warp min/max
    float mn = w, mx = w;
    #pragma unroll
    for (int o = 16; o; o >>= 1) {
        mn = fminf(mn, __shfl_xor_sync(0xFFFFFFFFu, mn, o));
        mx = fmaxf(mx, __shfl_xor_sync(0xFFFFFFFFu, mx, o));
    }
    if (lane == 0) {
        mn = fminf(mn, 0.0f);
        mx = fmaxf(mx, 0.0f);
        s_mn[sub]        = mn;
        s_scale_raw[sub] = __fdiv_rn(fmaxf(mx - mn, 1e-8f), 15.0f);
    }
    __syncthreads();

    // 6-bit quantization of the 8 sub-scales (computed redundantly per thread)
    float smin = s_scale_raw[0], smax = s_scale_raw[0];
    #pragma unroll
    for (int i = 1; i < 8; i++) {
        smin = fminf(smin, s_scale_raw[i]);
        smax = fmaxf(smax, s_scale_raw[i]);
    }
    const float srange = fmaxf(smax - smin, 1e-8f);
    const float sr     = s_scale_raw[sub];
    float s_int = fminf(fmaxf(rintf(__fdiv_rn(sr - smin, srange) * 63.0f), 0.0f), 63.0f);
    float sq    = __fdiv_rn(s_int, 63.0f) * srange + smin;
    float sb    = fmaxf(sq, 1e-8f);

    const float mn2 = s_mn[sub];
    float q  = fminf(fmaxf(rintf(__fdiv_rn(w - mn2, sb)), 0.0f), 15.0f);
    float dq = q * sb + mn2;

    // round-to-nearest tf32 so the mma (which truncates) behaves as RN
    uint32_t t;
    asm("cvt.rna.tf32.f32 %0, %1;" : "=r"(t) : "f"(dq));
    g_fqw[base + tid] = __uint_as_float(t);
}

// ---------------------------------------------------------------------------
// Kernel 2: rna tf32 rounding of x (removes truncation bias in the mma)
// ---------------------------------------------------------------------------
__global__ void round_x_kernel(const float4* __restrict__ in, int n4)
{
    int i = blockIdx.x * blockDim.x + threadIdx.x;
    if (i >= n4) return;
    float4 v = in[i];
    uint32_t a, b, c, d;
    asm("cvt.rna.tf32.f32 %0, %1;" : "=r"(a) : "f"(v.x));
    asm("cvt.rna.tf32.f32 %0, %1;" : "=r"(b) : "f"(v.y));
    asm("cvt.rna.tf32.f32 %0, %1;" : "=r"(c) : "f"(v.z));
    asm("cvt.rna.tf32.f32 %0, %1;" : "=r"(d) : "f"(v.w));
    float4 o;
    o.x = __uint_as_float(a); o.y = __uint_as_float(b);
    o.z = __uint_as_float(c); o.w = __uint_as_float(d);
    reinterpret_cast<float4*>(g_xr)[i] = o;
}

// ---------------------------------------------------------------------------
// Kernel 3: GEMM  C[m,n] = sum_k Xr[m,k] * Wfq[n,k] + bias[n]
// 128x128x32 CTA tile, 8 warps (2x4), warp tile 64x32, tf32 m16n8k8,
// cp.async double buffer, stride-36 SMEM (conflict-free fragment LDS).
// ---------------------------------------------------------------------------
#define BM 128
#define BN 128
#define BK 32
#define SSTRIDE 36
#define TILE_ELEMS (128 * SSTRIDE)
#define SMEM_BYTES (4 * TILE_ELEMS * 4)

__device__ __forceinline__ void cp16(void* s, const void* g)
{
    uint32_t sa = (uint32_t)__cvta_generic_to_shared(s);
    asm volatile("cp.async.cg.shared.global [%0], [%1], 16;" :: "r"(sa), "l"(g));
}

__global__ void __launch_bounds__(256)
gemm_tf32_kernel(const float* __restrict__ bias, float* __restrict__ C)
{
    extern __shared__ float smem[];
    float* sAbuf[2] = { smem,                  smem + TILE_ELEMS     };
    float* sBbuf[2] = { smem + 2 * TILE_ELEMS, smem + 3 * TILE_ELEMS };

    const int tid  = threadIdx.x;
    const int warp = tid >> 5;
    const int lane = tid & 31;
    const int gid  = lane >> 2;   // groupID   (0..7)
    const int tig  = lane & 3;    // thread in group (0..3)

    // grid swizzle: GROUP_M=8 m-tiles per group for L2 reuse
    const int GRID_N  = N_DIM / BN;           // 32
    const int GROUP_M = 8;
    const int gsz   = GROUP_M * GRID_N;       // 256
    int tile  = blockIdx.x;
    int group = tile / gsz;
    int inb   = tile - group * gsz;
    int bm    = group * GROUP_M + (inb % GROUP_M);
    int bn    = inb / GROUP_M;

    const float* Ag = g_xr  + (size_t)bm * BM * K_DIM;
    const float* Bg = g_fqw + (size_t)bn * BN * K_DIM;

    const int wm = (warp >> 2) * 64;   // warp m offset in CTA tile
    const int wn = (warp & 3)  * 32;   // warp n offset

    float acc[4][4][4];
    #pragma unroll
    for (int i = 0; i < 4; i++)
        #pragma unroll
        for (int j = 0; j < 4; j++)
            #pragma unroll
            for (int r = 0; r < 4; r++) acc[i][j][r] = 0.0f;

    auto load_tile = [&](const float* __restrict__ g, float* __restrict__ s, int kofs) {
        #pragma unroll
        for (int i = 0; i < 4; i++) {
            int c   = tid + i * 256;     // 1024 16B-chunks per tile
            int row = c >> 3;            // 8 chunks per row
            int kc  = (c & 7) * 4;
            cp16(s + row * SSTRIDE + kc, g + (size_t)row * K_DIM + kofs + kc);
        }
    };

    load_tile(Ag, sAbuf[0], 0);
    load_tile(Bg, sBbuf[0], 0);
    asm volatile("cp.async.commit_group;");

    const int NK = K_DIM / BK;  // 128
    for (int it = 0; it < NK; ++it) {
        const int cur = it & 1;
        if (it + 1 < NK) {
            load_tile(Ag, sAbuf[cur ^ 1], (it + 1) * BK);
            load_tile(Bg, sBbuf[cur ^ 1], (it + 1) * BK);
            asm volatile("cp.async.commit_group;");
            asm volatile("cp.async.wait_group 1;");
        } else {
            asm volatile("cp.async.wait_group 0;");
        }
        __syncthreads();

        const float* a = sAbuf[cur];
        const float* b = sBbuf[cur];

        #pragma unroll
        for (int ks = 0; ks < 4; ++ks) {
            const int k0 = ks * 8;
            uint32_t af[4][4], bf[4][2];
            #pragma unroll
            for (int mt = 0; mt < 4; ++mt) {
                int m = wm + mt * 16 + gid;
                af[mt][0] = __float_as_uint(a[m       * SSTRIDE + k0 + tig    ]);
                af[mt][1] = __float_as_uint(a[(m + 8) * SSTRIDE + k0 + tig    ]);
                af[mt][2] = __float_as_uint(a[m       * SSTRIDE + k0 + tig + 4]);
                af[mt][3] = __float_as_uint(a[(m + 8) * SSTRIDE + k0 + tig + 4]);
            }
            #pragma unroll
            for (int nt = 0; nt < 4; ++nt) {
                int n = wn + nt * 8 + gid;
                bf[nt][0] = __float_as_uint(b[n * SSTRIDE + k0 + tig    ]);
                bf[nt][1] = __float_as_uint(b[n * SSTRIDE + k0 + tig + 4]);
            }
            #pragma unroll
            for (int mt = 0; mt < 4; ++mt)
                #pragma unroll
                for (int nt = 0; nt < 4; ++nt) {
                    asm volatile(
                        "mma.sync.aligned.m16n8k8.row.col.f32.tf32.tf32.f32 "
                        "{%0,%1,%2,%3}, {%4,%5,%6,%7}, {%8,%9}, {%0,%1,%2,%3};"
                        : "+f"(acc[mt][nt][0]), "+f"(acc[mt][nt][1]),
                          "+f"(acc[mt][nt][2]), "+f"(acc[mt][nt][3])
                        : "r"(af[mt][0]), "r"(af[mt][1]), "r"(af[mt][2]), "r"(af[mt][3]),
                          "r"(bf[nt][0]), "r"(bf[nt][1]));
                }
        }
        __syncthreads();
    }

    // epilogue: add bias, write fp32
    #pragma unroll
    for (int nt = 0; nt < 4; ++nt) {
        int n = bn * BN + wn + nt * 8 + tig * 2;
        float b0 = bias[n], b1 = bias[n + 1];
        #pragma unroll
        for (int mt = 0; mt < 4; ++mt) {
            int m = bm * BM + wm + mt * 16 + gid;
            float2 v0 = make_float2(acc[mt][nt][0] + b0, acc[mt][nt][1] + b1);
            float2 v1 = make_float2(acc[mt][nt][2] + b0, acc[mt][nt][3] + b1);
            *reinterpret_cast<float2*>(C + (size_t)m       * N_DIM + n) = v0;
            *reinterpret_cast<float2*>(C + (size_t)(m + 8) * N_DIM + n) = v1;
        }
    }
}

// ---------------------------------------------------------------------------
extern "C" void kernel_launch(void* const* d_in, const int* in_sizes, int n_in,
                              void* d_out, int out_size)
{
    const float* x    = (const float*)d_in[0];   // (2,2048,4096)
    const float* w    = (const float*)d_in[1];   // (4096,4096)
    const float* bias = (const float*)d_in[2];   // (4096,)
    float* out = (float*)d_out;

    // 1) fake-quant W  (65536 blocks of 256)
    dequant_kernel<<<(N_DIM * K_DIM) / 256, 256>>>(w);

    // 2) tf32-round x
    const int n4 = (M_DIM * K_DIM) / 4;
    round_x_kernel<<<(n4 + 255) / 256, 256>>>((const float4*)x, n4);

    // 3) GEMM + bias
    cudaFuncSetAttribute(gemm_tf32_kernel,
                         cudaFuncAttributeMaxDynamicSharedMemorySize, SMEM_BYTES);
    const int grid = (M_DIM / BM) * (N_DIM / BN);  // 1024
    gemm_tf32_kernel<<<grid, 256, SMEM_BYTES>>>(bias, out);
}

// round 4
// speedup vs baseline: 2.0545x; 2.0545x over previous
#include <cuda_runtime.h>
#include <cuda_fp16.h>
#include <cstdint>

#define M_DIM 4096
#define N_DIM 4096
#define K_DIM 4096

// Scratch (__device__ globals: allocation-free rule)
__device__ __half g_fqw[(size_t)N_DIM * K_DIM];   // fake-quantized W, fp16
__device__ __half g_xh [(size_t)M_DIM * K_DIM];   // x, fp16

// ---------------------------------------------------------------------------
// Kernel 1: Q4_K_M fake-quant. One WARP per 256-elem block, 8 elems/lane,
// fp16 output. sub-block s (32 elems) = lanes [4s, 4s+4).
// ---------------------------------------------------------------------------
__global__ void __launch_bounds__(256) dequant_kernel(const float4* __restrict__ W4)
{
    const int gw   = blockIdx.x * 8 + (threadIdx.x >> 5);
    const int lane = threadIdx.x & 31;
    const size_t b4 = (size_t)gw * 64 + lane * 2;

    float4 v0 = W4[b4];
    float4 v1 = W4[b4 + 1];

    float mn = fminf(fminf(fminf(v0.x, v0.y), fminf(v0.z, v0.w)),
                     fminf(fminf(v1.x, v1.y), fminf(v1.z, v1.w)));
    float mx = fmaxf(fmaxf(fmaxf(v0.x, v0.y), fmaxf(v0.z, v0.w)),
                     fmaxf(fmaxf(v1.x, v1.y), fmaxf(v1.z, v1.w)));
    // reduce within 4-lane sub-block group
    mn = fminf(mn, __shfl_xor_sync(0xFFFFFFFFu, mn, 1));
    mn = fminf(mn, __shfl_xor_sync(0xFFFFFFFFu, mn, 2));
    mx = fmaxf(mx, __shfl_xor_sync(0xFFFFFFFFu, mx, 1));
    mx = fmaxf(mx, __shfl_xor_sync(0xFFFFFFFFu, mx, 2));
    mn = fminf(mn, 0.0f);
    mx = fmaxf(mx, 0.0f);

    float sr = __fdiv_rn(fmaxf(mx - mn, 1e-8f), 15.0f);

    // 6-bit quant of the 8 sub-scales: warp-wide min/max (uniform per 4-lane group)
    float smin = sr, smax = sr;
    #pragma unroll
    for (int o = 4; o < 32; o <<= 1) {
        smin = fminf(smin, __shfl_xor_sync(0xFFFFFFFFu, smin, o));
        smax = fmaxf(smax, __shfl_xor_sync(0xFFFFFFFFu, smax, o));
    }
    const float srange = fmaxf(smax - smin, 1e-8f);
    float si = fminf(fmaxf(rintf(__fdiv_rn(sr - smin, srange) * 63.0f), 0.0f), 63.0f);
    float sq = __fdiv_rn(si, 63.0f) * srange + smin;
    float sb = fmaxf(sq, 1e-8f);
    float inv = __fdiv_rn(1.0f, sb);

    auto dq = [&](float w) -> float {
        float q = fminf(fmaxf(rintf((w - mn) * inv), 0.0f), 15.0f);
        return q * sb + mn;
    };
    __half2 h[4];
    h[0] = __floats2half2_rn(dq(v0.x), dq(v0.y));
    h[1] = __floats2half2_rn(dq(v0.z), dq(v0.w));
    h[2] = __floats2half2_rn(dq(v1.x), dq(v1.y));
    h[3] = __floats2half2_rn(dq(v1.z), dq(v1.w));
    reinterpret_cast<uint4*>(g_fqw)[(size_t)gw * 32 + lane] = *reinterpret_cast<uint4*>(h);
}

// ---------------------------------------------------------------------------
// Kernel 2: x -> fp16 (8 elems / thread, 16B stores)
// ---------------------------------------------------------------------------
__global__ void __launch_bounds__(256) convert_x_kernel(const float4* __restrict__ in)
{
    const size_t i = (size_t)blockIdx.x * blockDim.x + threadIdx.x;
    float4 a = in[i * 2];
    float4 b = in[i * 2 + 1];
    __half2 h[4];
    h[0] = __floats2half2_rn(a.x, a.y);
    h[1] = __floats2half2_rn(a.z, a.w);
    h[2] = __floats2half2_rn(b.x, b.y);
    h[3] = __floats2half2_rn(b.z, b.w);
    reinterpret_cast<uint4*>(g_xh)[i] = *reinterpret_cast<uint4*>(h);
}

// ---------------------------------------------------------------------------
// Kernel 3: fp16 GEMM  C[m,n] = sum_k X[m,k] * W[n,k] + bias[n]
// 128x128 CTA tile, BK=64 halves (128B rows, SW128 xor swizzle),
// double-buffered cp.async, ldmatrix fragments, m16n8k16 HMMA, fp32 accum.
// ---------------------------------------------------------------------------
#define BM 128
#define BN 128
#define BK 64
#define STAGE_BYTES 32768               // 16KB A + 16KB B
#define SMEM_TOTAL (2 * STAGE_BYTES)    // 65536
#define NK (K_DIM / BK)                 // 64
#define SWZ(o) ((o) ^ (((o) >> 3) & 0x70))

__device__ __forceinline__ void cp16s(uint32_t s, const void* g)
{
    asm volatile("cp.async.cg.shared.global [%0], [%1], 16;" :: "r"(s), "l"(g));
}
#define LDSM_X4(r0, r1, r2, r3, a) \
    asm volatile("ldmatrix.sync.aligned.m8n8.x4.shared.b16 {%0,%1,%2,%3}, [%4];" \
                 : "=r"(r0), "=r"(r1), "=r"(r2), "=r"(r3) : "r"(a))

__global__ void __launch_bounds__(256, 2)
gemm_fp16_kernel(const float* __restrict__ bias, float* __restrict__ C)
{
    extern __shared__ char smem[];
    const uint32_t sbase = (uint32_t)__cvta_generic_to_shared(smem);

    const int tid  = threadIdx.x;
    const int warp = tid >> 5;
    const int lane = tid & 31;
    const int gid  = lane >> 2;
    const int tig  = lane & 3;

    // grid swizzle: GROUP_M=8 m-tiles per group for L2 reuse
    const int GRID_N  = N_DIM / BN;     // 32
    const int GROUP_M = 8;
    const int gsz = GROUP_M * GRID_N;   // 256
    int tile  = blockIdx.x;
    int group = tile / gsz;
    int inb   = tile - group * gsz;
    int bm    = group * GROUP_M + (inb % GROUP_M);
    int bn    = inb / GROUP_M;

    const __half* Ag = g_xh  + (size_t)bm * BM * K_DIM;
    const __half* Bg = g_fqw + (size_t)bn * BN * K_DIM;

    const int wm = (warp >> 2) * 64;
    const int wn = (warp & 3)  * 32;

    float acc[4][4][4];
    #pragma unroll
    for (int i = 0; i < 4; i++)
        #pragma unroll
        for (int j = 0; j < 4; j++)
            #pragma unroll
            for (int r = 0; r < 4; r++) acc[i][j][r] = 0.0f;

    // per-stage layout: A @ s*32768, B @ s*32768 + 16384
    auto load_tile = [&](const __half* __restrict__ g, uint32_t sdst, int kofs) {
        #pragma unroll
        for (int i = 0; i < 4; i++) {
            int c   = tid + i * 256;          // 1024 chunks of 16B
            int row = c >> 3;
            int kc  = (c & 7) * 8;            // halves
            cp16s(sdst + SWZ(row * 128 + (c & 7) * 16),
                  g + (size_t)row * K_DIM + kofs + kc);
        }
    };

    load_tile(Ag, sbase, 0);
    load_tile(Bg, sbase + 16384, 0);
    asm volatile("cp.async.commit_group;");

    for (int it = 0; it < NK; ++it) {
        const int cur = it & 1;
        if (it + 1 < NK) {
            uint32_t nb = sbase + (cur ^ 1) * STAGE_BYTES;
            load_tile(Ag, nb,         (it + 1) * BK);
            load_tile(Bg, nb + 16384, (it + 1) * BK);
            asm volatile("cp.async.commit_group;");
            asm volatile("cp.async.wait_group 1;");
        } else {
            asm volatile("cp.async.wait_group 0;");
        }
        __syncthreads();

        const uint32_t aB = sbase + cur * STAGE_BYTES;
        const uint32_t bB = aB + 16384;

        #pragma unroll
        for (int ks = 0; ks < 4; ++ks) {
            const int kb = ks * 32;           // byte offset of k0 = ks*16 halves
            uint32_t af[4][4], bf[4][2];
            #pragma unroll
            for (int mt = 0; mt < 4; ++mt) {
                int row = wm + mt * 16 + (lane & 15);
                uint32_t off = row * 128 + kb + ((lane >> 4) << 4);
                LDSM_X4(af[mt][0], af[mt][1], af[mt][2], af[mt][3], aB + SWZ(off));
            }
            #pragma unroll
            for (int nt2 = 0; nt2 < 2; ++nt2) {
                int nrow = wn + nt2 * 16 + (lane & 7) + ((lane & 16) >> 1);
                uint32_t off = nrow * 128 + kb + ((lane & 8) << 1);
                uint32_t r0, r1, r2, r3;
                LDSM_X4(r0, r1, r2, r3, bB + SWZ(off));
                bf[nt2 * 2][0]     = r0; bf[nt2 * 2][1]     = r1;
                bf[nt2 * 2 + 1][0] = r2; bf[nt2 * 2 + 1][1] = r3;
            }
            #pragma unroll
            for (int mt = 0; mt < 4; ++mt)
                #pragma unroll
                for (int nt = 0; nt < 4; ++nt) {
                    asm volatile(
                        "mma.sync.aligned.m16n8k16.row.col.f32.f16.f16.f32 "
                        "{%0,%1,%2,%3}, {%4,%5,%6,%7}, {%8,%9}, {%0,%1,%2,%3};"
                        : "+f"(acc[mt][nt][0]), "+f"(acc[mt][nt][1]),
                          "+f"(acc[mt][nt][2]), "+f"(acc[mt][nt][3])
                        : "r"(af[mt][0]), "r"(af[mt][1]), "r"(af[mt][2]), "r"(af[mt][3]),
                          "r"(bf[nt][0]), "r"(bf[nt][1]));
                }
        }
        __syncthreads();
    }

    // epilogue: bias add, fp32 stores
    #pragma unroll
    for (int nt = 0; nt < 4; ++nt) {
        int n = bn * BN + wn + nt * 8 + tig * 2;
        float b0 = bias[n], b1 = bias[n + 1];
        #pragma unroll
        for (int mt = 0; mt < 4; ++mt) {
            int m = bm * BM + wm + mt * 16 + gid;
            float2 v0 = make_float2(acc[mt][nt][0] + b0, acc[mt][nt][1] + b1);
            float2 v1 = make_float2(acc[mt][nt][2] + b0, acc[mt][nt][3] + b1);
            *reinterpret_cast<float2*>(C + (size_t)m       * N_DIM + n) = v0;
            *reinterpret_cast<float2*>(C + (size_t)(m + 8) * N_DIM + n) = v1;
        }
    }
}

// ---------------------------------------------------------------------------
extern "C" void kernel_launch(void* const* d_in, const int* in_sizes, int n_in,
                              void* d_out, int out_size)
{
    const float* x    = (const float*)d_in[0];
    const float* w    = (const float*)d_in[1];
    const float* bias = (const float*)d_in[2];
    float* out = (float*)d_out;

    // 1) fake-quant W -> fp16 (65536 blocks of 256, 1 warp each)
    dequant_kernel<<<8192, 256>>>((const float4*)w);

    // 2) x -> fp16
    convert_x_kernel<<<(M_DIM * K_DIM / 8) / 256, 256>>>((const float4*)x);

    // 3) fp16 GEMM + bias
    cudaFuncSetAttribute(gemm_fp16_kernel,
                         cudaFuncAttributeMaxDynamicSharedMemorySize, SMEM_TOTAL);
    const int grid = (M_DIM / BM) * (N_DIM / BN);  // 1024
    gemm_fp16_kernel<<<grid, 256, SMEM_TOTAL>>>(bias, out);
}